// round 17
// baseline (speedup 1.0000x reference)
#include <cuda_runtime.h>
#include <cuda_bf16.h>
#include <math_constants.h>

#define N 512
#define D 64
#define MAX_STEPS 10
#define BT_LDM 72         // bf16 per W2^T row (144 B; ldmatrix conflict-free, pad unread)

// ---- persistent scratch ----
__device__ float         g_p0[N];
__device__ unsigned int  g_cand[MAX_STEPS][N];  // per-step candidate maxima (float bits)
__device__ float         g_rowconst[N * D];     // nf[i]@W1[0:64] + b1
// Bt per j-tile, XOR-swizzled fragment layout:
// float2 slot [k2][ j ^ ((k2&3)<<3) ] = (bt[2k2][j], bt[2k2+1][j])
__device__ __align__(16) float g_Bt2[16][D * 32];
__device__ float         g_f0[N];
__device__ __align__(16) __nv_bfloat16 g_w2hiT[32 * BT_LDM]; // [m][k] transposed, padded
__device__ __align__(16) __nv_bfloat16 g_w2loT[32 * BT_LDM]; // exact residual, transposed

// ---- mma / ldmatrix helpers ----
__device__ __forceinline__ unsigned smem_u32(const void* p) {
    return (unsigned)__cvta_generic_to_shared(p);
}
__device__ __forceinline__ void ldm_x4(unsigned& r0, unsigned& r1, unsigned& r2, unsigned& r3,
                                       unsigned addr) {
    asm volatile("ldmatrix.sync.aligned.m8n8.x4.shared.b16 {%0,%1,%2,%3}, [%4];"
                 : "=r"(r0), "=r"(r1), "=r"(r2), "=r"(r3) : "r"(addr));
}
__device__ __forceinline__ void mma_bf16(float* d, const unsigned* a, unsigned b0, unsigned b1) {
    asm volatile("mma.sync.aligned.m16n8k16.row.col.f32.bf16.bf16.f32 "
                 "{%0,%1,%2,%3}, {%4,%5,%6,%7}, {%8,%9}, {%0,%1,%2,%3};"
                 : "+f"(d[0]), "+f"(d[1]), "+f"(d[2]), "+f"(d[3])
                 : "r"(a[0]), "r"(a[1]), "r"(a[2]), "r"(a[3]), "r"(b0), "r"(b1));
}

// ---------------------------------------------------------------------------
// Merged init: rowconst, Bt (swizzled), f0, W2 split, p0, cand-clear.
__global__ void k_init_ab(const float* __restrict__ nf,
                          const float* __restrict__ W1,
                          const float* __restrict__ b1,
                          const float* __restrict__ W2,
                          const int* __restrict__ shock, int n_shock) {
    int gid = blockIdx.x * 256 + threadIdx.x;      // < 32768
    int i = gid >> 6, k = gid & 63;
    float accA = b1[k];
#pragma unroll 8
    for (int d = 0; d < D; d++) accA = fmaf(nf[i * D + d], W1[d * D + k], accA);
    g_rowconst[gid] = accA;

    int j = gid & (N - 1), kk = gid >> 9;          // kk < 64
    float accB = 0.f;
#pragma unroll 8
    for (int d = 0; d < D; d++) accB = fmaf(nf[j * D + d], W1[(D + d) * D + kk], accB);
    {   // XOR-swizzled fragment layout
        int jl = j & 31, k2 = kk >> 1, par = kk & 1;
        int j2 = jl ^ ((k2 & 3) << 3);
        g_Bt2[j >> 5][(k2 * 32 + j2) * 2 + par] = accB;
    }

    if (gid < N) {
        g_f0[gid] = nf[gid * D];
        float p = 0.f;
        for (int t = 0; t < n_shock; t++) if (shock[t] == gid) p = 1.f;
        g_p0[gid] = p;
    }
    if (gid < MAX_STEPS * N) (&g_cand[0][0])[gid] = 0u;
    if (gid < D * 32) {                            // W2 split, transposed to [m][k]
        int kw = gid >> 5, m = gid & 31;
        float w = W2[gid];                         // W2 row-major [k][m]
        __nv_bfloat16 h = __float2bfloat16(w);
        g_w2hiT[m * BT_LDM + kw] = h;
        g_w2loT[m * BT_LDM + kw] = __float2bfloat16(w - __bfloat162float(h));
    }
}

// ---------------------------------------------------------------------------
// Step kernel: 256 threads = 8 warps. Warp w: row r=w&3, j-half jh=w>>2 (16 j).
// One m16 tile per warp (acc 16 regs) -> ~75 regs -> 3 blocks/SM (24 warps).
__global__ void __launch_bounds__(256, 3)
k_edges(const float* __restrict__ cgm, const float* __restrict__ W1,
        const float* __restrict__ b2,  const float* __restrict__ W3,
        const float* __restrict__ b3,  int step, float sf) {
    __shared__ __align__(32) unsigned char pool[19520];
    __nv_bfloat16* s_bhT = (__nv_bfloat16*)(pool);
    __nv_bfloat16* s_blT = (__nv_bfloat16*)(pool + 4608);
    float* s_bt2 = (float*)(pool + 9216);
    float* s_rv = (float*)(pool + 17408);
    float* s_wq = (float*)(pool + 18432);
    float2* s_bw = (float2*)(pool + 18944);
    float* s_f0j = (float*)(pool + 19200);
    float* s_f0i = (float*)(pool + 19328);
    float* s_pi  = (float*)(pool + 19344);
    unsigned* s_cand = (unsigned*)(pool + 19360);
    float* s_b3p = (float*)(pool + 19488);
    int* s_alive = (int*)(pool + 19492);

    int tid = threadIdx.x;
    int warp = tid >> 5, lane = tid & 31;
    int r = warp & 3, jh = warp >> 2;
    int j0 = blockIdx.x * 32;
    int i0 = blockIdx.y * 4;

    if (tid == 0) *s_alive = 0;
    __syncthreads();
    if (tid < 4) {
        float p = g_p0[i0 + tid];                  // replay: p_s = max(p0, cand_0..s-1)
        for (int s = 0; s < step; s++)
            p = fmaxf(p, __uint_as_float(g_cand[s][i0 + tid]));
        s_pi[tid] = p;
        s_f0i[tid] = g_f0[i0 + tid];
        if (p > 0.f) atomicExch(s_alive, 1);
    }
    __syncthreads();
    if (!*s_alive) return;                         // all 4 rows dead (block-uniform)

    {   // prologue — vectorized, 256 threads
        const uint4* w2h4 = (const uint4*)g_w2hiT; // 288 uint4 each
        const uint4* w2l4 = (const uint4*)g_w2loT;
        uint4* sb0 = (uint4*)s_bhT;
        uint4* sb1 = (uint4*)s_blT;
        for (int idx = tid; idx < 288; idx += 256) {
            sb0[idx] = w2h4[idx];
            sb1[idx] = w2l4[idx];
        }
        const float4* bt4 = (const float4*)&g_Bt2[blockIdx.x][0]; // 512 float4
        float4* sbt4 = (float4*)s_bt2;
#pragma unroll
        for (int q = 0; q < 2; q++) sbt4[tid + 256 * q] = bt4[tid + 256 * q];
        {   // 4*D = 256 rv entries
            int rr = tid >> 6, k = tid & 63;
            s_rv[tid] = fmaf(s_pi[rr], W1[129 * D + k],
                        fmaf(sf, W1[130 * D + k], g_rowconst[(i0 + rr) * D + k]));
        }
        if (tid < 128) s_wq[tid] = W1[(128 + 3 * (tid & 1)) * D + (tid >> 1)];
        if (tid < 32) { s_bw[tid] = make_float2(b2[tid], W3[tid]);
                        s_f0j[tid] = g_f0[j0 + tid]; s_cand[tid] = 0u; }
        if (tid == 0) *s_b3p = b3[0];
    }
    __syncthreads();

    float p_i = s_pi[r];                           // warp-uniform guard
    if (p_i > 0.f) {
        int jl16 = jh * 16 + (lane & 15);
        float cg = cgm[(i0 + r) * N + j0 + jl16];
        float fd = fabsf(s_f0i[r] - s_f0j[jl16]);

        int g = lane >> 2, c = lane & 3;
        // redistribute cg/fd to fragment rows: edge 8h+g (within this warp's 16)
        float cg_r[2], fd_r[2];
#pragma unroll
        for (int h = 0; h < 2; h++) {
            int src = 8 * h + g;                   // lanes 0-15 hold edges 0-15
            cg_r[h] = __shfl_sync(0xFFFFFFFFu, cg, src);
            fd_r[h] = __shfl_sync(0xFFFFFFFFu, fd, src);
        }

        const float2* rv2 = (const float2*)(s_rv + r * D);
        const float4* wq4 = (const float4*)s_wq;
        const float2* bt2f = (const float2*)s_bt2;

        // B ldmatrix addressing (identical to validated version)
        int midx = lane >> 3, r8 = lane & 7;
        unsigned boff = (unsigned)((((midx >> 1) * 8 + r8) * 144) + (midx & 1) * 16);
        unsigned aBh = smem_u32(s_bhT) + boff;
        unsigned aBl = smem_u32(s_blT) + boff;

        float acc[4][4];                           // [nt][reg]
#pragma unroll
        for (int nt = 0; nt < 4; nt++)
#pragma unroll
            for (int q = 0; q < 4; q++) acc[nt][q] = 0.f;

#pragma unroll
        for (int ks = 0; ks < 4; ks++) {
            int k2a = 8 * ks + c, k2b = k2a + 4;   // both have (k2&3)==c
            float2 rvA = rv2[k2a], rvB = rv2[k2b];
            float4 wqA = wq4[k2a], wqB = wq4[k2b];

            unsigned fa_hi[4], fa_lo[4];
#pragma unroll
            for (int h = 0; h < 2; h++) {
                int jj = jh * 16 + 8 * h + g;      // fragment row -> j_local
                int jA = jj ^ (c << 3);            // bake-time swizzle
                float2 btA = bt2f[k2a * 32 + jA];
                float2 btB = bt2f[k2b * 32 + jA];
                float cgv = cg_r[h], fdv = fd_r[h];
                // k-pair A (k = 16ks+2c, +1)
                float hA0 = fmaxf(fmaf(cgv, wqA.x, fmaf(fdv, wqA.y, rvA.x + btA.x)), 0.f);
                float hA1 = fmaxf(fmaf(cgv, wqA.z, fmaf(fdv, wqA.w, rvA.y + btA.y)), 0.f);
                unsigned hb;
                asm("cvt.rn.bf16x2.f32 %0, %1, %2;" : "=r"(hb) : "f"(hA1), "f"(hA0));
                float fl = __uint_as_float(hb << 16);
                float fh = __uint_as_float(hb & 0xFFFF0000u);
                unsigned lb;
                asm("cvt.rn.bf16x2.f32 %0, %1, %2;" : "=r"(lb)
                    : "f"(hA1 - fh), "f"(hA0 - fl));
                fa_hi[h] = hb; fa_lo[h] = lb;
                // k-pair B (k = 16ks+8+2c, +1)
                float hB0 = fmaxf(fmaf(cgv, wqB.x, fmaf(fdv, wqB.y, rvB.x + btB.x)), 0.f);
                float hB1 = fmaxf(fmaf(cgv, wqB.z, fmaf(fdv, wqB.w, rvB.y + btB.y)), 0.f);
                unsigned hb2;
                asm("cvt.rn.bf16x2.f32 %0, %1, %2;" : "=r"(hb2) : "f"(hB1), "f"(hB0));
                float fl2 = __uint_as_float(hb2 << 16);
                float fh2 = __uint_as_float(hb2 & 0xFFFF0000u);
                unsigned lb2;
                asm("cvt.rn.bf16x2.f32 %0, %1, %2;" : "=r"(lb2)
                    : "f"(hB1 - fh2), "f"(hB0 - fl2));
                fa_hi[2 + h] = hb2; fa_lo[2 + h] = lb2;
            }

            // ---- B fragments (unchanged) ----
            unsigned fb_hi[2][4], fb_lo[2][4];
            unsigned kb = (unsigned)(ks * 32);     // 16 k elems = 32 B
            ldm_x4(fb_hi[0][0], fb_hi[0][1], fb_hi[0][2], fb_hi[0][3], aBh + kb);
            ldm_x4(fb_hi[1][0], fb_hi[1][1], fb_hi[1][2], fb_hi[1][3], aBh + kb + 16 * 144);
            ldm_x4(fb_lo[0][0], fb_lo[0][1], fb_lo[0][2], fb_lo[0][3], aBl + kb);
            ldm_x4(fb_lo[1][0], fb_lo[1][1], fb_lo[1][2], fb_lo[1][3], aBl + kb + 16 * 144);

            // ---- 3-pass mma: hi.hi + lo.hi + hi.lo ----
#pragma unroll
            for (int nt = 0; nt < 4; nt++) {
                unsigned bh0 = fb_hi[nt >> 1][(nt & 1) * 2];
                unsigned bh1 = fb_hi[nt >> 1][(nt & 1) * 2 + 1];
                unsigned bl0 = fb_lo[nt >> 1][(nt & 1) * 2];
                unsigned bl1 = fb_lo[nt >> 1][(nt & 1) * 2 + 1];
                mma_bf16(acc[nt], fa_hi, bh0, bh1);
                mma_bf16(acc[nt], fa_lo, bh0, bh1);
                mma_bf16(acc[nt], fa_hi, bl0, bl1);
            }
        }

        // ---- register epilogue ----
        int c2 = (lane & 3) * 2;
        float zp[2] = {0.f, 0.f};                  // [rowhalf]
#pragma unroll
        for (int nt = 0; nt < 4; nt++) {
            float2 bw0 = s_bw[nt * 8 + c2];
            float2 bw1 = s_bw[nt * 8 + c2 + 1];
            zp[0] = fmaf(fmaxf(acc[nt][0] + bw0.x, 0.f), bw0.y, zp[0]);
            zp[0] = fmaf(fmaxf(acc[nt][1] + bw1.x, 0.f), bw1.y, zp[0]);
            zp[1] = fmaf(fmaxf(acc[nt][2] + bw0.x, 0.f), bw0.y, zp[1]);
            zp[1] = fmaf(fmaxf(acc[nt][3] + bw1.x, 0.f), bw1.y, zp[1]);
        }
#pragma unroll
        for (int h = 0; h < 2; h++) {
            zp[h] += __shfl_xor_sync(0xFFFFFFFFu, zp[h], 1);
            zp[h] += __shfl_xor_sync(0xFFFFFFFFu, zp[h], 2);
        }
        // route z of edge (lane&15) = 8h+g': h=(lane>>3)&1, g'=lane&7, src=4*g'
        int src = (lane & 7) * 4;
        float s0 = __shfl_sync(0xFFFFFFFFu, zp[0], src);
        float s1 = __shfl_sync(0xFFFFFFFFu, zp[1], src);
        float zj = (lane & 8) ? s1 : s0;
        float z = zj + *s_b3p;
        float tr = 1.f / (1.f + __expf(-z));
        float val = (cg > 0.f) ? p_i * tr * cg : 0.f;
        if (val > 0.f && lane < 16)
            atomicMax(&s_cand[jl16], __float_as_uint(val));   // uint==float order, >=0
    }
    __syncthreads();
    if (tid < 32) {
        unsigned v = s_cand[tid];
        if (v) atomicMax(&g_cand[step][j0 + tid], v);
    }
}

// replay the 10-step max/arr recurrence exactly; write output
__global__ void k_final(float* __restrict__ out) {
    int j = threadIdx.x;                            // 512 threads
    float p = g_p0[j];
    float arr = (p > 0.f) ? 0.f : CUDART_INF_F;
#pragma unroll
    for (int s = 0; s < MAX_STEPS; s++) {
        float c = __uint_as_float(g_cand[s][j]);
        if (c > p) { p = c; arr = fminf(arr, (float)(s + 1)); }
    }
    out[j] = p; out[N + j] = arr;
}

// ---------------------------------------------------------------------------
extern "C" void kernel_launch(void* const* d_in, const int* in_sizes, int n_in,
                              void* d_out, int out_size) {
    const float* cg    = (const float*)d_in[0];
    const float* nf    = (const float*)d_in[1];
    const int*   shock = (const int*)  d_in[2];
    const float* W1    = (const float*)d_in[3];
    const float* b1    = (const float*)d_in[4];
    const float* W2    = (const float*)d_in[5];
    const float* b2    = (const float*)d_in[6];
    const float* W3    = (const float*)d_in[7];
    const float* b3    = (const float*)d_in[8];
    float* out = (float*)d_out;

    k_init_ab<<<128, 256>>>(nf, W1, b1, W2, shock, in_sizes[2]);
    for (int s = 0; s < MAX_STEPS; s++)
        k_edges<<<dim3(16, 128), 256>>>(cg, W1, b2, W3, b3,
                                        s, (float)s / (float)MAX_STEPS);
    k_final<<<1, 512>>>(out);
}